// round 10
// baseline (speedup 1.0000x reference)
#include <cuda_runtime.h>
#include <cuda_fp16.h>
#include <cstdint>

// Problem constants
#define BB 4
#define SS 2048
#define DD 1024
#define HH 16
#define HD 64
#define NT (BB * SS)        // 8192 tokens
#define D3 (3 * DD)         // 3072

#define WSC 64.0f           // weight scale 2^6
#define IWSC (1.0f / 64.0f)

// ---------------------------------------------------------------------------
// Scratch (device globals — no runtime allocation)
// ---------------------------------------------------------------------------
static __device__ __half g_qkv[(size_t)NT * D3];
static __device__ __half g_x  [(size_t)NT * DD];
static __device__ __half g_a  [(size_t)NT * DD];
static __device__ __half g_wq [(size_t)D3 * DD];   // c_attn_w^T *64 [N][K]
static __device__ __half g_wp [(size_t)DD * DD];

// ---------------------------------------------------------------------------
__device__ __forceinline__ uint32_t smem_u32(const void* p) {
    uint32_t a;
    asm("{ .reg .u64 t; cvta.to.shared.u64 t, %1; cvt.u32.u64 %0, t; }" : "=r"(a) : "l"(p));
    return a;
}

#define CP_ASYNC16(saddr, gptr) \
    asm volatile("cp.async.cg.shared.global [%0], [%1], 16;" :: "r"(saddr), "l"(gptr) : "memory")
#define CP_COMMIT()  asm volatile("cp.async.commit_group;" ::: "memory")
#define CP_WAIT0()   asm volatile("cp.async.wait_group 0;" ::: "memory")
#define CP_WAIT1()   asm volatile("cp.async.wait_group 1;" ::: "memory")

#define LDMATRIX_X4(r0, r1, r2, r3, addr) \
    asm volatile("ldmatrix.sync.aligned.m8n8.x4.shared.b16 {%0,%1,%2,%3}, [%4];" \
        : "=r"(r0), "=r"(r1), "=r"(r2), "=r"(r3) : "r"(addr))

#define LDMATRIX_X4_T(r0, r1, r2, r3, addr) \
    asm volatile("ldmatrix.sync.aligned.m8n8.x4.trans.shared.b16 {%0,%1,%2,%3}, [%4];" \
        : "=r"(r0), "=r"(r1), "=r"(r2), "=r"(r3) : "r"(addr))

#define MMA_F16(c, a, b) \
    asm volatile("mma.sync.aligned.m16n8k16.row.col.f32.f16.f16.f32 " \
        "{%0,%1,%2,%3}, {%4,%5,%6,%7}, {%8,%9}, {%0,%1,%2,%3};" \
        : "+f"((c)[0]), "+f"((c)[1]), "+f"((c)[2]), "+f"((c)[3]) \
        : "r"((a)[0]), "r"((a)[1]), "r"((a)[2]), "r"((a)[3]), "r"((b)[0]), "r"((b)[1]))

__device__ __forceinline__ uint32_t pack_f16(float a, float b) {
    __half2 t = __floats2half2_rn(a, b);
    return *reinterpret_cast<uint32_t*>(&t);
}

// ---------------------------------------------------------------------------
// Conversion kernels
// ---------------------------------------------------------------------------
__global__ void act_h(const float4* __restrict__ x, uint2* __restrict__ o, int n4) {
    int i = blockIdx.x * blockDim.x + threadIdx.x;
    if (i >= n4) return;
    float4 v = x[i];
    uint2 r;
    r.x = pack_f16(v.x, v.y);
    r.y = pack_f16(v.z, v.w);
    o[i] = r;
}

__global__ void wt_h(const float* __restrict__ W, __half* __restrict__ o, int K, int N) {
    __shared__ float t[32][33];
    const int kb = blockIdx.y * 32, nb = blockIdx.x * 32;
    const int tx = threadIdx.x, ty = threadIdx.y;
#pragma unroll
    for (int i = 0; i < 32; i += 8)
        t[ty + i][tx] = W[(size_t)(kb + ty + i) * N + nb + tx];
    __syncthreads();
#pragma unroll
    for (int i = 0; i < 32; i += 8)
        o[(size_t)(nb + ty + i) * K + kb + tx] = __float2half_rn(t[tx][ty + i] * WSC);
}

// ---------------------------------------------------------------------------
// f16 HMMA GEMM v4 (unchanged from R9): 128x128 CTA, 4 warps, 64x64/warp,
// BK=64, 3-stage ring, one barrier/stage, 2 CTAs/SM.
// ---------------------------------------------------------------------------
#define GROWB 144
#define GATILE (128 * GROWB)           // 18432
#define GSTAGE (2 * GATILE)            // 36864
#define GSMEM  (3 * GSTAGE)            // 110592

extern __shared__ char g_dsmem[];

__global__ void __launch_bounds__(128, 2) gemm_mma(
    const __half* __restrict__ A, const __half* __restrict__ B,
    const float* __restrict__ bias, float* __restrict__ Cf,
    __half* __restrict__ Ch, int M, int N, int K)
{
    const int tid  = threadIdx.x;
    const int wid  = tid >> 5;
    const int lane = tid & 31;
    const int wm   = wid >> 1;
    const int wn   = wid & 1;
    const int bm = blockIdx.y, bn = blockIdx.x;

    const __half* Ab = A + (size_t)(bm * 128) * K;
    const __half* Bb = B + (size_t)(bn * 128) * K;

    const uint32_t sb = smem_u32(g_dsmem);

    float acc[4][8][4];
#pragma unroll
    for (int i = 0; i < 4; i++)
#pragma unroll
        for (int j = 0; j < 8; j++)
#pragma unroll
            for (int v = 0; v < 4; v++) acc[i][j][v] = 0.0f;

    const int NS = K >> 6;

    auto load_stage = [&](int s, int buf) {
        const int k0 = s << 6;
        const uint32_t base = sb + buf * GSTAGE;
#pragma unroll
        for (int i = 0; i < 8; i++) {
            const int idx = i * 128 + tid;
            const int r = idx >> 3, c = idx & 7;
            CP_ASYNC16(base + r * GROWB + c * 16, Ab + (size_t)r * K + k0 + c * 8);
        }
#pragma unroll
        for (int i = 0; i < 8; i++) {
            const int idx = i * 128 + tid;
            const int r = idx >> 3, c = idx & 7;
            CP_ASYNC16(base + GATILE + r * GROWB + c * 16, Bb + (size_t)r * K + k0 + c * 8);
        }
        CP_COMMIT();
    };

    load_stage(0, 0);
    load_stage(1, 1);

    const int a_row  = (lane & 15);
    const int a_koff = (lane >> 4) * 16;
    const int b_blk  = lane >> 3;
    const int b_row8 = lane & 7;
    const int b_noff = ((b_blk >> 1) << 3) + b_row8;
    const int b_koff = (b_blk & 1) * 16;

    for (int s = 0; s < NS; s++) {
        if (s < NS - 1) CP_WAIT1();
        else            CP_WAIT0();
        __syncthreads();
        if (s + 2 < NS) load_stage(s + 2, (s + 2) % 3);

        const uint32_t st = sb + (s % 3) * GSTAGE;
#pragma unroll
        for (int ks = 0; ks < 4; ks++) {
            const int kb = ks * 32;

            uint32_t af[4][4], bf[8][2];
#pragma unroll
            for (int mt = 0; mt < 4; mt++) {
                const uint32_t ar = st + (wm * 64 + mt * 16 + a_row) * GROWB + kb + a_koff;
                LDMATRIX_X4(af[mt][0], af[mt][1], af[mt][2], af[mt][3], ar);
            }
#pragma unroll
            for (int p = 0; p < 4; p++) {
                const uint32_t br = st + GATILE +
                    (wn * 64 + p * 16 + b_noff) * GROWB + kb + b_koff;
                LDMATRIX_X4(bf[2 * p][0], bf[2 * p][1], bf[2 * p + 1][0], bf[2 * p + 1][1], br);
            }
#pragma unroll
            for (int mt = 0; mt < 4; mt++)
#pragma unroll
                for (int nt = 0; nt < 8; nt++)
                    MMA_F16(acc[mt][nt], af[mt], bf[nt]);
        }
    }

    const int r0 = bm * 128 + wm * 64 + (lane >> 2);
    const int c0 = bn * 128 + wn * 64 + (lane & 3) * 2;
    if (Cf) {
#pragma unroll
        for (int mt = 0; mt < 4; mt++)
#pragma unroll
            for (int nt = 0; nt < 8; nt++) {
                const int row = r0 + mt * 16;
                const int col = c0 + nt * 8;
                float2 o0, o1;
                o0.x = acc[mt][nt][0] * IWSC + bias[col];
                o0.y = acc[mt][nt][1] * IWSC + bias[col + 1];
                o1.x = acc[mt][nt][2] * IWSC + bias[col];
                o1.y = acc[mt][nt][3] * IWSC + bias[col + 1];
                *(float2*)(Cf + (size_t)row * N + col) = o0;
                *(float2*)(Cf + (size_t)(row + 8) * N + col) = o1;
            }
    } else {
#pragma unroll
        for (int mt = 0; mt < 4; mt++)
#pragma unroll
            for (int nt = 0; nt < 8; nt++) {
                const int row = r0 + mt * 16;
                const int col = c0 + nt * 8;
                const float b0 = bias[col], b1 = bias[col + 1];
                *(uint32_t*)(Ch + (size_t)row * N + col) =
                    pack_f16(acc[mt][nt][0] * IWSC + b0, acc[mt][nt][1] * IWSC + b1);
                *(uint32_t*)(Ch + (size_t)(row + 8) * N + col) =
                    pack_f16(acc[mt][nt][2] * IWSC + b0, acc[mt][nt][3] * IWSC + b1);
            }
    }
}

// ---------------------------------------------------------------------------
// Tensor-core causal flash attention v2: 128-key tiles (double MMA density
// per barrier window; softmax rescale amortized over 2x keys).
// CTA: 128 q rows of one (b,h); 8 warps x 16 rows.
// ---------------------------------------------------------------------------
#define AROWB 144
#define AKTILE (128 * AROWB)           // 18432 (128 keys x 64 dims f16)
#define ASTAGE (2 * AKTILE)            // K|V = 36864
#define ASMEM (2 * ASTAGE)             // 73728

__global__ void __launch_bounds__(256) attn_mma(
    const __half* __restrict__ QKV, __half* __restrict__ O)
{
    const int tid  = threadIdx.x;
    const int wid  = tid >> 5;
    const int lane = tid & 31;
    const int qtile = (gridDim.x - 1) - blockIdx.x;   // heavy tiles first
    const int bh = blockIdx.y;
    const int b  = bh >> 4;
    const int h  = bh & 15;
    const int bS = b * SS;
    const int qbase = qtile * 128 + wid * 16;

    const uint32_t sb = smem_u32(g_dsmem);

    // stage Q (128 rows x 64 dims f16)
#pragma unroll
    for (int i = 0; i < 4; i++) {
        const int idx = i * 256 + tid;
        const int r = idx >> 3, c = idx & 7;
        const size_t g = (size_t)(bS + qtile * 128 + r) * D3 + h * HD + c * 8;
        CP_ASYNC16(sb + r * AROWB + c * 16, QKV + g);
    }
    CP_COMMIT();
    CP_WAIT0();
    __syncthreads();

    uint32_t qf[4][4];
    const int a_row  = lane & 15;
    const int a_koff = (lane >> 4) * 16;
    {
        const uint32_t qr = sb + (wid * 16 + a_row) * AROWB + a_koff;
#pragma unroll
        for (int ks = 0; ks < 4; ks++)
            LDMATRIX_X4(qf[ks][0], qf[ks][1], qf[ks][2], qf[ks][3], qr + ks * 32);
    }
    __syncthreads();   // Q region reused for K/V

    // K/V tile loader: 128 keys, K then V (2048 x 16B chunks, 8/thread)
    auto load_kv = [&](int kt, int buf) {
        const int k0 = kt * 128;
        const uint32_t base = sb + buf * ASTAGE;
#pragma unroll
        for (int i = 0; i < 8; i++) {
            const int idx  = i * 256 + tid;     // 0..2047
            const int tile = idx >> 10;         // 0=K, 1=V
            const int r    = (idx >> 3) & 127;
            const int c    = idx & 7;
            const size_t g = (size_t)(bS + k0 + r) * D3 +
                             (tile ? 2 * DD : DD) + h * HD + c * 8;
            CP_ASYNC16(base + tile * AKTILE + r * AROWB + c * 16, QKV + g);
        }
        CP_COMMIT();
    };

    float o[8][4];
#pragma unroll
    for (int n = 0; n < 8; n++)
#pragma unroll
        for (int j = 0; j < 4; j++) o[n][j] = 0.0f;
    float mrow[2] = {-1e30f, -1e30f};
    float lrow[2] = {0.0f, 0.0f};

    const int b_blk  = lane >> 3;
    const int b_row8 = lane & 7;
    const int b_noff = ((b_blk >> 1) << 3) + b_row8;
    const int b_koff = (b_blk & 1) * 16;
    const int v_row  = lane & 15;
    const int v_coff = ((lane >> 4) & 1) * 16;

    const int ntl = qtile + 1;      // 128-key tiles up to & including diagonal
    load_kv(0, 0);

    for (int kt = 0; kt < ntl; kt++) {
        const int buf = kt & 1;
        const int k0 = kt * 128;
        if (kt + 1 < ntl) { load_kv(kt + 1, buf ^ 1); CP_WAIT1(); }
        else              { CP_WAIT0(); }
        __syncthreads();

        if (k0 <= qbase + 15) {     // warp has unmasked work
            const uint32_t kbse = sb + buf * ASTAGE;
            const uint32_t vbse = kbse + AKTILE;

            // S = Q K^T  (16 q rows x 128 keys)
            float s[16][4];
#pragma unroll
            for (int n = 0; n < 16; n++)
#pragma unroll
                for (int j = 0; j < 4; j++) s[n][j] = 0.0f;

#pragma unroll
            for (int p = 0; p < 8; p++) {
#pragma unroll
                for (int ks = 0; ks < 4; ks++) {
                    uint32_t kf[4];
                    const uint32_t ar = kbse + (p * 16 + b_noff) * AROWB + ks * 32 + b_koff;
                    LDMATRIX_X4(kf[0], kf[1], kf[2], kf[3], ar);
                    uint32_t b0[2] = {kf[0], kf[1]}, b1[2] = {kf[2], kf[3]};
                    MMA_F16(s[2 * p],     qf[ks], b0);
                    MMA_F16(s[2 * p + 1], qf[ks], b1);
                }
            }

            // masking + online softmax
            const bool need_mask = (k0 + 127 > qbase);
            const int row0 = qbase + (lane >> 2);
            const int colb = k0 + (lane & 3) * 2;
#pragma unroll
            for (int hf = 0; hf < 2; hf++) {
                const int row = row0 + 8 * hf;
                float mx = mrow[hf];
#pragma unroll
                for (int n = 0; n < 16; n++) {
                    float v0 = s[n][2 * hf]     * 0.125f;
                    float v1 = s[n][2 * hf + 1] * 0.125f;
                    if (need_mask) {
                        const int col = colb + 8 * n;
                        if (col > row)     v0 = -1e30f;
                        if (col + 1 > row) v1 = -1e30f;
                    }
                    s[n][2 * hf] = v0; s[n][2 * hf + 1] = v1;
                    mx = fmaxf(mx, fmaxf(v0, v1));
                }
                mx = fmaxf(mx, __shfl_xor_sync(0xffffffffu, mx, 1));
                mx = fmaxf(mx, __shfl_xor_sync(0xffffffffu, mx, 2));
                const float alpha = __expf(mrow[hf] - mx);
                lrow[hf] *= alpha;
#pragma unroll
                for (int n = 0; n < 8; n++) {
                    o[n][2 * hf]     *= alpha;
                    o[n][2 * hf + 1] *= alpha;
                }
                float ls = 0.0f;
#pragma unroll
                for (int n = 0; n < 16; n++) {
                    const float p0 = __expf(s[n][2 * hf]     - mx);
                    const float p1 = __expf(s[n][2 * hf + 1] - mx);
                    s[n][2 * hf] = p0; s[n][2 * hf + 1] = p1;
                    ls += p0 + p1;
                }
                lrow[hf] += ls;
                mrow[hf] = mx;
            }

            // O += P V  (128 keys = 8 k16 steps)
#pragma unroll
            for (int ks = 0; ks < 8; ks++) {
                uint32_t pf[4];
#pragma unroll
                for (int q2 = 0; q2 < 2; q2++) {
                    const float* pv = s[2 * ks + q2];
                    pf[q2 * 2]     = pack_f16(pv[0], pv[1]);
                    pf[q2 * 2 + 1] = pack_f16(pv[2], pv[3]);
                }
#pragma unroll
                for (int np = 0; np < 4; np++) {
                    uint32_t vf[4];
                    const uint32_t va = vbse + (ks * 16 + v_row) * AROWB + np * 32 + v_coff;
                    LDMATRIX_X4_T(vf[0], vf[1], vf[2], vf[3], va);
                    uint32_t v0[2] = {vf[0], vf[1]}, v1[2] = {vf[2], vf[3]};
                    MMA_F16(o[2 * np],     pf, v0);
                    MMA_F16(o[2 * np + 1], pf, v1);
                }
            }
        }
        __syncthreads();
    }

    float inv[2];
#pragma unroll
    for (int hf = 0; hf < 2; hf++) {
        float l = lrow[hf];
        l += __shfl_xor_sync(0xffffffffu, l, 1);
        l += __shfl_xor_sync(0xffffffffu, l, 2);
        inv[hf] = 1.0f / l;
    }
    const int row0 = qbase + (lane >> 2);
    const int colb = h * HD + (lane & 3) * 2;
#pragma unroll
    for (int hf = 0; hf < 2; hf++) {
        const size_t rof = (size_t)(bS + row0 + 8 * hf) * DD;
#pragma unroll
        for (int n = 0; n < 8; n++)
            *(uint32_t*)(O + rof + colb + n * 8) =
                pack_f16(o[n][2 * hf] * inv[hf], o[n][2 * hf + 1] * inv[hf]);
    }
}

// ---------------------------------------------------------------------------
extern "C" void kernel_launch(void* const* d_in, const int* in_sizes, int n_in,
                              void* d_out, int out_size)
{
    const float* hidden   = (const float*)d_in[0];
    const float* c_attn_w = (const float*)d_in[1];
    const float* c_attn_b = (const float*)d_in[2];
    const float* c_proj_w = (const float*)d_in[3];
    const float* c_proj_b = (const float*)d_in[4];
    float* out = (float*)d_out;

    __half *qkv, *x, *a, *wq, *wp;
    cudaGetSymbolAddress((void**)&qkv, g_qkv);
    cudaGetSymbolAddress((void**)&x,   g_x);
    cudaGetSymbolAddress((void**)&a,   g_a);
    cudaGetSymbolAddress((void**)&wq,  g_wq);
    cudaGetSymbolAddress((void**)&wp,  g_wp);

    cudaFuncSetAttribute(gemm_mma, cudaFuncAttributeMaxDynamicSharedMemorySize, GSMEM);
    cudaFuncSetAttribute(attn_mma, cudaFuncAttributeMaxDynamicSharedMemorySize, ASMEM);

    wt_h<<<dim3(D3 / 32, DD / 32), dim3(32, 8)>>>(c_attn_w, wq, DD, D3);
    wt_h<<<dim3(DD / 32, DD / 32), dim3(32, 8)>>>(c_proj_w, wp, DD, DD);

    {
        const int n4 = NT * DD / 4;
        act_h<<<(n4 + 255) / 256, 256>>>((const float4*)hidden, (uint2*)x, n4);
    }

    // 1) QKV projection -> f16
    gemm_mma<<<dim3(D3 / 128, NT / 128), 128, GSMEM>>>(
        x, wq, c_attn_b, nullptr, qkv, NT, D3, DD);

    // 2) causal flash attention (128-key tiles) -> f16
    attn_mma<<<dim3(SS / 128, BB * HH), 256, ASMEM>>>(qkv, a);

    // 3) output projection -> fp32
    gemm_mma<<<dim3(DD / 128, NT / 128), 128, GSMEM>>>(
        a, wp, c_proj_b, out, nullptr, NT, DD, DD);
}

// round 11
// speedup vs baseline: 1.2043x; 1.2043x over previous
#include <cuda_runtime.h>
#include <cuda_fp16.h>
#include <cstdint>

// Problem constants
#define BB 4
#define SS 2048
#define DD 1024
#define HH 16
#define HD 64
#define NT (BB * SS)        // 8192 tokens
#define D3 (3 * DD)         // 3072

#define WSC 64.0f           // weight scale 2^6
#define IWSC (1.0f / 64.0f)
#define QSCALE 0.1803368801f   // 0.125 * log2(e)

// ---------------------------------------------------------------------------
// Scratch (device globals — no runtime allocation)
// ---------------------------------------------------------------------------
static __device__ __half g_qkv[(size_t)NT * D3];
static __device__ __half g_x  [(size_t)NT * DD];
static __device__ __half g_a  [(size_t)NT * DD];
static __device__ __half g_wq [(size_t)D3 * DD];   // c_attn_w^T *64 [N][K]
static __device__ __half g_wp [(size_t)DD * DD];

// ---------------------------------------------------------------------------
__device__ __forceinline__ uint32_t smem_u32(const void* p) {
    uint32_t a;
    asm("{ .reg .u64 t; cvta.to.shared.u64 t, %1; cvt.u32.u64 %0, t; }" : "=r"(a) : "l"(p));
    return a;
}
__device__ __forceinline__ float ex2(float x) {
    float r;
    asm("ex2.approx.f32 %0, %1;" : "=f"(r) : "f"(x));
    return r;
}

#define CP_ASYNC16(saddr, gptr) \
    asm volatile("cp.async.cg.shared.global [%0], [%1], 16;" :: "r"(saddr), "l"(gptr) : "memory")
#define CP_COMMIT()  asm volatile("cp.async.commit_group;" ::: "memory")
#define CP_WAIT0()   asm volatile("cp.async.wait_group 0;" ::: "memory")
#define CP_WAIT1()   asm volatile("cp.async.wait_group 1;" ::: "memory")

#define LDMATRIX_X4(r0, r1, r2, r3, addr) \
    asm volatile("ldmatrix.sync.aligned.m8n8.x4.shared.b16 {%0,%1,%2,%3}, [%4];" \
        : "=r"(r0), "=r"(r1), "=r"(r2), "=r"(r3) : "r"(addr))

#define LDMATRIX_X4_T(r0, r1, r2, r3, addr) \
    asm volatile("ldmatrix.sync.aligned.m8n8.x4.trans.shared.b16 {%0,%1,%2,%3}, [%4];" \
        : "=r"(r0), "=r"(r1), "=r"(r2), "=r"(r3) : "r"(addr))

#define MMA_F16(c, a, b) \
    asm volatile("mma.sync.aligned.m16n8k16.row.col.f32.f16.f16.f32 " \
        "{%0,%1,%2,%3}, {%4,%5,%6,%7}, {%8,%9}, {%0,%1,%2,%3};" \
        : "+f"((c)[0]), "+f"((c)[1]), "+f"((c)[2]), "+f"((c)[3]) \
        : "r"((a)[0]), "r"((a)[1]), "r"((a)[2]), "r"((a)[3]), "r"((b)[0]), "r"((b)[1]))

__device__ __forceinline__ uint32_t pack_f16(float a, float b) {
    __half2 t = __floats2half2_rn(a, b);
    return *reinterpret_cast<uint32_t*>(&t);
}

// ---------------------------------------------------------------------------
// Conversion kernels
// ---------------------------------------------------------------------------
__global__ void act_h(const float4* __restrict__ x, uint2* __restrict__ o, int n4) {
    int i = blockIdx.x * blockDim.x + threadIdx.x;
    if (i >= n4) return;
    float4 v = x[i];
    uint2 r;
    r.x = pack_f16(v.x, v.y);
    r.y = pack_f16(v.z, v.w);
    o[i] = r;
}

__global__ void wt_h(const float* __restrict__ W, __half* __restrict__ o, int K, int N) {
    __shared__ float t[32][33];
    const int kb = blockIdx.y * 32, nb = blockIdx.x * 32;
    const int tx = threadIdx.x, ty = threadIdx.y;
#pragma unroll
    for (int i = 0; i < 32; i += 8)
        t[ty + i][tx] = W[(size_t)(kb + ty + i) * N + nb + tx];
    __syncthreads();
#pragma unroll
    for (int i = 0; i < 32; i += 8)
        o[(size_t)(nb + ty + i) * K + kb + tx] = __float2half_rn(t[tx][ty + i] * WSC);
}

// ---------------------------------------------------------------------------
// f16 HMMA GEMM v4 (unchanged from R9): 128x128 CTA, 4 warps, 64x64/warp,
// BK=64, 3-stage ring, one barrier/stage, 2 CTAs/SM.
// ---------------------------------------------------------------------------
#define GROWB 144
#define GATILE (128 * GROWB)           // 18432
#define GSTAGE (2 * GATILE)            // 36864
#define GSMEM  (3 * GSTAGE)            // 110592

extern __shared__ char g_dsmem[];

__global__ void __launch_bounds__(128, 2) gemm_mma(
    const __half* __restrict__ A, const __half* __restrict__ B,
    const float* __restrict__ bias, float* __restrict__ Cf,
    __half* __restrict__ Ch, int M, int N, int K)
{
    const int tid  = threadIdx.x;
    const int wid  = tid >> 5;
    const int lane = tid & 31;
    const int wm   = wid >> 1;
    const int wn   = wid & 1;
    const int bm = blockIdx.y, bn = blockIdx.x;

    const __half* Ab = A + (size_t)(bm * 128) * K;
    const __half* Bb = B + (size_t)(bn * 128) * K;

    const uint32_t sb = smem_u32(g_dsmem);

    float acc[4][8][4];
#pragma unroll
    for (int i = 0; i < 4; i++)
#pragma unroll
        for (int j = 0; j < 8; j++)
#pragma unroll
            for (int v = 0; v < 4; v++) acc[i][j][v] = 0.0f;

    const int NS = K >> 6;

    auto load_stage = [&](int s, int buf) {
        const int k0 = s << 6;
        const uint32_t base = sb + buf * GSTAGE;
#pragma unroll
        for (int i = 0; i < 8; i++) {
            const int idx = i * 128 + tid;
            const int r = idx >> 3, c = idx & 7;
            CP_ASYNC16(base + r * GROWB + c * 16, Ab + (size_t)r * K + k0 + c * 8);
        }
#pragma unroll
        for (int i = 0; i < 8; i++) {
            const int idx = i * 128 + tid;
            const int r = idx >> 3, c = idx & 7;
            CP_ASYNC16(base + GATILE + r * GROWB + c * 16, Bb + (size_t)r * K + k0 + c * 8);
        }
        CP_COMMIT();
    };

    load_stage(0, 0);
    load_stage(1, 1);

    const int a_row  = (lane & 15);
    const int a_koff = (lane >> 4) * 16;
    const int b_blk  = lane >> 3;
    const int b_row8 = lane & 7;
    const int b_noff = ((b_blk >> 1) << 3) + b_row8;
    const int b_koff = (b_blk & 1) * 16;

    for (int s = 0; s < NS; s++) {
        if (s < NS - 1) CP_WAIT1();
        else            CP_WAIT0();
        __syncthreads();
        if (s + 2 < NS) load_stage(s + 2, (s + 2) % 3);

        const uint32_t st = sb + (s % 3) * GSTAGE;
#pragma unroll
        for (int ks = 0; ks < 4; ks++) {
            const int kb = ks * 32;

            uint32_t af[4][4], bf[8][2];
#pragma unroll
            for (int mt = 0; mt < 4; mt++) {
                const uint32_t ar = st + (wm * 64 + mt * 16 + a_row) * GROWB + kb + a_koff;
                LDMATRIX_X4(af[mt][0], af[mt][1], af[mt][2], af[mt][3], ar);
            }
#pragma unroll
            for (int p = 0; p < 4; p++) {
                const uint32_t br = st + GATILE +
                    (wn * 64 + p * 16 + b_noff) * GROWB + kb + b_koff;
                LDMATRIX_X4(bf[2 * p][0], bf[2 * p][1], bf[2 * p + 1][0], bf[2 * p + 1][1], br);
            }
#pragma unroll
            for (int mt = 0; mt < 4; mt++)
#pragma unroll
                for (int nt = 0; nt < 8; nt++)
                    MMA_F16(acc[mt][nt], af[mt], bf[nt]);
        }
    }

    const int r0 = bm * 128 + wm * 64 + (lane >> 2);
    const int c0 = bn * 128 + wn * 64 + (lane & 3) * 2;
    if (Cf) {
#pragma unroll
        for (int mt = 0; mt < 4; mt++)
#pragma unroll
            for (int nt = 0; nt < 8; nt++) {
                const int row = r0 + mt * 16;
                const int col = c0 + nt * 8;
                float2 o0, o1;
                o0.x = acc[mt][nt][0] * IWSC + bias[col];
                o0.y = acc[mt][nt][1] * IWSC + bias[col + 1];
                o1.x = acc[mt][nt][2] * IWSC + bias[col];
                o1.y = acc[mt][nt][3] * IWSC + bias[col + 1];
                *(float2*)(Cf + (size_t)row * N + col) = o0;
                *(float2*)(Cf + (size_t)(row + 8) * N + col) = o1;
            }
    } else {
#pragma unroll
        for (int mt = 0; mt < 4; mt++)
#pragma unroll
            for (int nt = 0; nt < 8; nt++) {
                const int row = r0 + mt * 16;
                const int col = c0 + nt * 8;
                const float b0 = bias[col], b1 = bias[col + 1];
                *(uint32_t*)(Ch + (size_t)row * N + col) =
                    pack_f16(acc[mt][nt][0] * IWSC + b0, acc[mt][nt][1] * IWSC + b1);
                *(uint32_t*)(Ch + (size_t)(row + 8) * N + col) =
                    pack_f16(acc[mt][nt][2] * IWSC + b0, acc[mt][nt][3] * IWSC + b1);
            }
    }
}

// ---------------------------------------------------------------------------
// Tensor-core causal flash attention v3: 64-key tiles (R9 structure) +
// base-2 softmax with scale folded into Q fragments + 3-stage single-barrier
// K/V ring.
// ---------------------------------------------------------------------------
#define AROWB 144
#define ATILE (64 * AROWB)             // 9216 (64 keys x 64 dims f16)
#define ASTAGE (2 * ATILE)             // K|V = 18432
#define ASMEM (3 * ASTAGE)             // 55296

__global__ void __launch_bounds__(256) attn_mma(
    const __half* __restrict__ QKV, __half* __restrict__ O)
{
    const int tid  = threadIdx.x;
    const int wid  = tid >> 5;
    const int lane = tid & 31;
    const int qtile = (gridDim.x - 1) - blockIdx.x;   // heavy tiles first
    const int bh = blockIdx.y;
    const int b  = bh >> 4;
    const int h  = bh & 15;
    const int bS = b * SS;
    const int qbase = qtile * 128 + wid * 16;

    const uint32_t sb = smem_u32(g_dsmem);

    // stage Q (128 rows x 64 dims f16) into first 18KB of smem
#pragma unroll
    for (int i = 0; i < 4; i++) {
        const int idx = i * 256 + tid;
        const int r = idx >> 3, c = idx & 7;
        const size_t g = (size_t)(bS + qtile * 128 + r) * D3 + h * HD + c * 8;
        CP_ASYNC16(sb + r * AROWB + c * 16, QKV + g);
    }
    CP_COMMIT();
    CP_WAIT0();
    __syncthreads();

    // Q fragments, pre-scaled by 0.125*log2(e) -> scores are base-2 logits
    uint32_t qf[4][4];
    const int a_row  = lane & 15;
    const int a_koff = (lane >> 4) * 16;
    {
        const uint32_t qr = sb + (wid * 16 + a_row) * AROWB + a_koff;
        const __half2 qs = __float2half2_rn(QSCALE);
#pragma unroll
        for (int ks = 0; ks < 4; ks++) {
            LDMATRIX_X4(qf[ks][0], qf[ks][1], qf[ks][2], qf[ks][3], qr + ks * 32);
#pragma unroll
            for (int j = 0; j < 4; j++) {
                __half2 v = *reinterpret_cast<__half2*>(&qf[ks][j]);
                v = __hmul2(v, qs);
                qf[ks][j] = *reinterpret_cast<uint32_t*>(&v);
            }
        }
    }
    __syncthreads();   // Q region reused for K/V ring

    auto load_kv = [&](int kt, int buf) {
        const int k0 = kt * 64;
        const uint32_t base = sb + buf * ASTAGE;
#pragma unroll
        for (int i = 0; i < 4; i++) {
            const int idx  = i * 256 + tid;     // 0..1023
            const int tile = idx >> 9;          // 0=K, 1=V
            const int r    = (idx >> 3) & 63;
            const int c    = idx & 7;
            const size_t g = (size_t)(bS + k0 + r) * D3 +
                             (tile ? 2 * DD : DD) + h * HD + c * 8;
            CP_ASYNC16(base + tile * ATILE + r * AROWB + c * 16, QKV + g);
        }
        CP_COMMIT();
    };

    float o[8][4];
#pragma unroll
    for (int n = 0; n < 8; n++)
#pragma unroll
        for (int j = 0; j < 4; j++) o[n][j] = 0.0f;
    float mrow[2] = {-1e30f, -1e30f};
    float lrow[2] = {0.0f, 0.0f};

    const int b_blk  = lane >> 3;
    const int b_row8 = lane & 7;
    const int b_noff = ((b_blk >> 1) << 3) + b_row8;
    const int b_koff = (b_blk & 1) * 16;
    const int v_row  = lane & 15;
    const int v_coff = ((lane >> 4) & 1) * 16;

    const int ntl = 2 * qtile + 2;
    load_kv(0, 0);
    if (ntl > 1) load_kv(1, 1);

    for (int kt = 0; kt < ntl; kt++) {
        if (kt < ntl - 1) CP_WAIT1();
        else              CP_WAIT0();
        __syncthreads();
        // buffer (kt+2)%3 == (kt-1)%3: its compute finished before the
        // barrier above, so refill needs no extra barrier.
        if (kt + 2 < ntl) load_kv(kt + 2, (kt + 2) % 3);

        const int k0 = kt * 64;
        if (k0 <= qbase + 15) {     // warp has unmasked work
            const uint32_t kbse = sb + (kt % 3) * ASTAGE;
            const uint32_t vbse = kbse + ATILE;

            // S = Q K^T (base-2 logits; scale already in Q)
            float s[8][4];
#pragma unroll
            for (int n = 0; n < 8; n++)
#pragma unroll
                for (int j = 0; j < 4; j++) s[n][j] = 0.0f;

#pragma unroll
            for (int p = 0; p < 4; p++) {
#pragma unroll
                for (int ks = 0; ks < 4; ks++) {
                    uint32_t kf[4];
                    const uint32_t ar = kbse + (p * 16 + b_noff) * AROWB + ks * 32 + b_koff;
                    LDMATRIX_X4(kf[0], kf[1], kf[2], kf[3], ar);
                    uint32_t b0[2] = {kf[0], kf[1]}, b1[2] = {kf[2], kf[3]};
                    MMA_F16(s[2 * p],     qf[ks], b0);
                    MMA_F16(s[2 * p + 1], qf[ks], b1);
                }
            }

            // masking + online softmax (base 2, bare EX2)
            const bool need_mask = (k0 + 63 > qbase);
            const int row0 = qbase + (lane >> 2);
            const int colb = k0 + (lane & 3) * 2;
#pragma unroll
            for (int hf = 0; hf < 2; hf++) {
                const int row = row0 + 8 * hf;
                float mx = mrow[hf];
                if (need_mask) {
#pragma unroll
                    for (int n = 0; n < 8; n++) {
                        const int col = colb + 8 * n;
                        if (col > row)     s[n][2 * hf]     = -1e30f;
                        if (col + 1 > row) s[n][2 * hf + 1] = -1e30f;
                    }
                }
#pragma unroll
                for (int n = 0; n < 8; n++)
                    mx = fmaxf(mx, fmaxf(s[n][2 * hf], s[n][2 * hf + 1]));
                mx = fmaxf(mx, __shfl_xor_sync(0xffffffffu, mx, 1));
                mx = fmaxf(mx, __shfl_xor_sync(0xffffffffu, mx, 2));
                const float alpha = ex2(mrow[hf] - mx);
                lrow[hf] *= alpha;
#pragma unroll
                for (int n = 0; n < 8; n++) {
                    o[n][2 * hf]     *= alpha;
                    o[n][2 * hf + 1] *= alpha;
                }
                float ls = 0.0f;
#pragma unroll
                for (int n = 0; n < 8; n++) {
                    const float p0 = ex2(s[n][2 * hf]     - mx);
                    const float p1 = ex2(s[n][2 * hf + 1] - mx);
                    s[n][2 * hf] = p0; s[n][2 * hf + 1] = p1;
                    ls += p0 + p1;
                }
                lrow[hf] += ls;
                mrow[hf] = mx;
            }

            // O += P V
#pragma unroll
            for (int ks = 0; ks < 4; ks++) {
                uint32_t pf[4];
#pragma unroll
                for (int q2 = 0; q2 < 2; q2++) {
                    const float* pv = s[2 * ks + q2];
                    pf[q2 * 2]     = pack_f16(pv[0], pv[1]);
                    pf[q2 * 2 + 1] = pack_f16(pv[2], pv[3]);
                }
#pragma unroll
                for (int np = 0; np < 4; np++) {
                    uint32_t vf[4];
                    const uint32_t va = vbse + (ks * 16 + v_row) * AROWB + np * 32 + v_coff;
                    LDMATRIX_X4_T(vf[0], vf[1], vf[2], vf[3], va);
                    uint32_t v0[2] = {vf[0], vf[1]}, v1[2] = {vf[2], vf[3]};
                    MMA_F16(o[2 * np],     pf, v0);
                    MMA_F16(o[2 * np + 1], pf, v1);
                }
            }
        }
    }

    float inv[2];
#pragma unroll
    for (int hf = 0; hf < 2; hf++) {
        float l = lrow[hf];
        l += __shfl_xor_sync(0xffffffffu, l, 1);
        l += __shfl_xor_sync(0xffffffffu, l, 2);
        inv[hf] = 1.0f / l;
    }
    const int row0 = qbase + (lane >> 2);
    const int colb = h * HD + (lane & 3) * 2;
#pragma unroll
    for (int hf = 0; hf < 2; hf++) {
        const size_t rof = (size_t)(bS + row0 + 8 * hf) * DD;
#pragma unroll
        for (int n = 0; n < 8; n++)
            *(uint32_t*)(O + rof + colb + n * 8) =
                pack_f16(o[n][2 * hf] * inv[hf], o[n][2 * hf + 1] * inv[hf]);
    }
}

// ---------------------------------------------------------------------------
extern "C" void kernel_launch(void* const* d_in, const int* in_sizes, int n_in,
                              void* d_out, int out_size)
{
    const float* hidden   = (const float*)d_in[0];
    const float* c_attn_w = (const float*)d_in[1];
    const float* c_attn_b = (const float*)d_in[2];
    const float* c_proj_w = (const float*)d_in[3];
    const float* c_proj_b = (const float*)d_in[4];
    float* out = (float*)d_out;

    __half *qkv, *x, *a, *wq, *wp;
    cudaGetSymbolAddress((void**)&qkv, g_qkv);
    cudaGetSymbolAddress((void**)&x,   g_x);
    cudaGetSymbolAddress((void**)&a,   g_a);
    cudaGetSymbolAddress((void**)&wq,  g_wq);
    cudaGetSymbolAddress((void**)&wp,  g_wp);

    cudaFuncSetAttribute(gemm_mma, cudaFuncAttributeMaxDynamicSharedMemorySize, GSMEM);
    cudaFuncSetAttribute(attn_mma, cudaFuncAttributeMaxDynamicSharedMemorySize, ASMEM);

    wt_h<<<dim3(D3 / 32, DD / 32), dim3(32, 8)>>>(c_attn_w, wq, DD, D3);
    wt_h<<<dim3(DD / 32, DD / 32), dim3(32, 8)>>>(c_proj_w, wp, DD, DD);

    {
        const int n4 = NT * DD / 4;
        act_h<<<(n4 + 255) / 256, 256>>>((const float4*)hidden, (uint2*)x, n4);
    }

    // 1) QKV projection -> f16
    gemm_mma<<<dim3(D3 / 128, NT / 128), 128, GSMEM>>>(
        x, wq, c_attn_b, nullptr, qkv, NT, D3, DD);

    // 2) causal flash attention (64-key tiles, base-2 softmax) -> f16
    attn_mma<<<dim3(SS / 128, BB * HH), 256, ASMEM>>>(qkv, a);

    // 3) output projection -> fp32
    gemm_mma<<<dim3(DD / 128, NT / 128), 128, GSMEM>>>(
        a, wp, c_proj_b, out, nullptr, NT, DD, DD);
}

// round 12
// speedup vs baseline: 1.2072x; 1.0024x over previous
#include <cuda_runtime.h>
#include <cuda_fp16.h>
#include <cstdint>

// Problem constants
#define BB 4
#define SS 2048
#define DD 1024
#define HH 16
#define HD 64
#define NT (BB * SS)        // 8192 tokens
#define D3 (3 * DD)         // 3072

#define WSC 64.0f           // weight scale 2^6
#define IWSC (1.0f / 64.0f)
#define QSCALE 0.1803368801f   // 0.125 * log2(e)

// ---------------------------------------------------------------------------
// Scratch (device globals — no runtime allocation)
// ---------------------------------------------------------------------------
static __device__ __half g_qkv[(size_t)NT * D3];
static __device__ __half g_x  [(size_t)NT * DD];
static __device__ __half g_a  [(size_t)NT * DD];
static __device__ __half g_wq [(size_t)D3 * DD];   // c_attn_w^T *64 [N][K]
static __device__ __half g_wp [(size_t)DD * DD];

// ---------------------------------------------------------------------------
__device__ __forceinline__ uint32_t smem_u32(const void* p) {
    uint32_t a;
    asm("{ .reg .u64 t; cvta.to.shared.u64 t, %1; cvt.u32.u64 %0, t; }" : "=r"(a) : "l"(p));
    return a;
}
__device__ __forceinline__ float ex2(float x) {
    float r;
    asm("ex2.approx.f32 %0, %1;" : "=f"(r) : "f"(x));
    return r;
}

#define CP_ASYNC16(saddr, gptr) \
    asm volatile("cp.async.cg.shared.global [%0], [%1], 16;" :: "r"(saddr), "l"(gptr) : "memory")
#define CP_COMMIT()  asm volatile("cp.async.commit_group;" ::: "memory")
#define CP_WAIT0()   asm volatile("cp.async.wait_group 0;" ::: "memory")
#define CP_WAIT1()   asm volatile("cp.async.wait_group 1;" ::: "memory")

#define LDMATRIX_X4(r0, r1, r2, r3, addr) \
    asm volatile("ldmatrix.sync.aligned.m8n8.x4.shared.b16 {%0,%1,%2,%3}, [%4];" \
        : "=r"(r0), "=r"(r1), "=r"(r2), "=r"(r3) : "r"(addr))

#define LDMATRIX_X4_T(r0, r1, r2, r3, addr) \
    asm volatile("ldmatrix.sync.aligned.m8n8.x4.trans.shared.b16 {%0,%1,%2,%3}, [%4];" \
        : "=r"(r0), "=r"(r1), "=r"(r2), "=r"(r3) : "r"(addr))

#define MMA_F16(c, a, b) \
    asm volatile("mma.sync.aligned.m16n8k16.row.col.f32.f16.f16.f32 " \
        "{%0,%1,%2,%3}, {%4,%5,%6,%7}, {%8,%9}, {%0,%1,%2,%3};" \
        : "+f"((c)[0]), "+f"((c)[1]), "+f"((c)[2]), "+f"((c)[3]) \
        : "r"((a)[0]), "r"((a)[1]), "r"((a)[2]), "r"((a)[3]), "r"((b)[0]), "r"((b)[1]))

__device__ __forceinline__ uint32_t pack_f16(float a, float b) {
    __half2 t = __floats2half2_rn(a, b);
    return *reinterpret_cast<uint32_t*>(&t);
}

// ---------------------------------------------------------------------------
// Conversion kernels
// ---------------------------------------------------------------------------
__global__ void act_h(const float4* __restrict__ x, uint2* __restrict__ o, int n4) {
    int i = blockIdx.x * blockDim.x + threadIdx.x;
    if (i >= n4) return;
    float4 v = x[i];
    uint2 r;
    r.x = pack_f16(v.x, v.y);
    r.y = pack_f16(v.z, v.w);
    o[i] = r;
}

__global__ void wt_h(const float* __restrict__ W, __half* __restrict__ o, int K, int N) {
    __shared__ float t[32][33];
    const int kb = blockIdx.y * 32, nb = blockIdx.x * 32;
    const int tx = threadIdx.x, ty = threadIdx.y;
#pragma unroll
    for (int i = 0; i < 32; i += 8)
        t[ty + i][tx] = W[(size_t)(kb + ty + i) * N + nb + tx];
    __syncthreads();
#pragma unroll
    for (int i = 0; i < 32; i += 8)
        o[(size_t)(nb + ty + i) * K + kb + tx] = __float2half_rn(t[tx][ty + i] * WSC);
}

// ---------------------------------------------------------------------------
// f16 HMMA GEMM v4 (frozen since R9): 128x128 CTA, 4 warps, 64x64/warp,
// BK=64, 3-stage ring, one barrier/stage, 2 CTAs/SM.
// ---------------------------------------------------------------------------
#define GROWB 144
#define GATILE (128 * GROWB)           // 18432
#define GSTAGE (2 * GATILE)            // 36864
#define GSMEM  (3 * GSTAGE)            // 110592

extern __shared__ char g_dsmem[];

__global__ void __launch_bounds__(128, 2) gemm_mma(
    const __half* __restrict__ A, const __half* __restrict__ B,
    const float* __restrict__ bias, float* __restrict__ Cf,
    __half* __restrict__ Ch, int M, int N, int K)
{
    const int tid  = threadIdx.x;
    const int wid  = tid >> 5;
    const int lane = tid & 31;
    const int wm   = wid >> 1;
    const int wn   = wid & 1;
    const int bm = blockIdx.y, bn = blockIdx.x;

    const __half* Ab = A + (size_t)(bm * 128) * K;
    const __half* Bb = B + (size_t)(bn * 128) * K;

    const uint32_t sb = smem_u32(g_dsmem);

    float acc[4][8][4];
#pragma unroll
    for (int i = 0; i < 4; i++)
#pragma unroll
        for (int j = 0; j < 8; j++)
#pragma unroll
            for (int v = 0; v < 4; v++) acc[i][j][v] = 0.0f;

    const int NS = K >> 6;

    auto load_stage = [&](int s, int buf) {
        const int k0 = s << 6;
        const uint32_t base = sb + buf * GSTAGE;
#pragma unroll
        for (int i = 0; i < 8; i++) {
            const int idx = i * 128 + tid;
            const int r = idx >> 3, c = idx & 7;
            CP_ASYNC16(base + r * GROWB + c * 16, Ab + (size_t)r * K + k0 + c * 8);
        }
#pragma unroll
        for (int i = 0; i < 8; i++) {
            const int idx = i * 128 + tid;
            const int r = idx >> 3, c = idx & 7;
            CP_ASYNC16(base + GATILE + r * GROWB + c * 16, Bb + (size_t)r * K + k0 + c * 8);
        }
        CP_COMMIT();
    };

    load_stage(0, 0);
    load_stage(1, 1);

    const int a_row  = (lane & 15);
    const int a_koff = (lane >> 4) * 16;
    const int b_blk  = lane >> 3;
    const int b_row8 = lane & 7;
    const int b_noff = ((b_blk >> 1) << 3) + b_row8;
    const int b_koff = (b_blk & 1) * 16;

    for (int s = 0; s < NS; s++) {
        if (s < NS - 1) CP_WAIT1();
        else            CP_WAIT0();
        __syncthreads();
        if (s + 2 < NS) load_stage(s + 2, (s + 2) % 3);

        const uint32_t st = sb + (s % 3) * GSTAGE;
#pragma unroll
        for (int ks = 0; ks < 4; ks++) {
            const int kb = ks * 32;

            uint32_t af[4][4], bf[8][2];
#pragma unroll
            for (int mt = 0; mt < 4; mt++) {
                const uint32_t ar = st + (wm * 64 + mt * 16 + a_row) * GROWB + kb + a_koff;
                LDMATRIX_X4(af[mt][0], af[mt][1], af[mt][2], af[mt][3], ar);
            }
#pragma unroll
            for (int p = 0; p < 4; p++) {
                const uint32_t br = st + GATILE +
                    (wn * 64 + p * 16 + b_noff) * GROWB + kb + b_koff;
                LDMATRIX_X4(bf[2 * p][0], bf[2 * p][1], bf[2 * p + 1][0], bf[2 * p + 1][1], br);
            }
#pragma unroll
            for (int mt = 0; mt < 4; mt++)
#pragma unroll
                for (int nt = 0; nt < 8; nt++)
                    MMA_F16(acc[mt][nt], af[mt], bf[nt]);
        }
    }

    const int r0 = bm * 128 + wm * 64 + (lane >> 2);
    const int c0 = bn * 128 + wn * 64 + (lane & 3) * 2;
    if (Cf) {
#pragma unroll
        for (int mt = 0; mt < 4; mt++)
#pragma unroll
            for (int nt = 0; nt < 8; nt++) {
                const int row = r0 + mt * 16;
                const int col = c0 + nt * 8;
                float2 o0, o1;
                o0.x = acc[mt][nt][0] * IWSC + bias[col];
                o0.y = acc[mt][nt][1] * IWSC + bias[col + 1];
                o1.x = acc[mt][nt][2] * IWSC + bias[col];
                o1.y = acc[mt][nt][3] * IWSC + bias[col + 1];
                *(float2*)(Cf + (size_t)row * N + col) = o0;
                *(float2*)(Cf + (size_t)(row + 8) * N + col) = o1;
            }
    } else {
#pragma unroll
        for (int mt = 0; mt < 4; mt++)
#pragma unroll
            for (int nt = 0; nt < 8; nt++) {
                const int row = r0 + mt * 16;
                const int col = c0 + nt * 8;
                const float b0 = bias[col], b1 = bias[col + 1];
                *(uint32_t*)(Ch + (size_t)row * N + col) =
                    pack_f16(acc[mt][nt][0] * IWSC + b0, acc[mt][nt][1] * IWSC + b1);
                *(uint32_t*)(Ch + (size_t)(row + 8) * N + col) =
                    pack_f16(acc[mt][nt][2] * IWSC + b0, acc[mt][nt][3] * IWSC + b1);
            }
    }
}

// ---------------------------------------------------------------------------
// Tensor-core causal flash attention v4: R11 structure + forced 2 CTAs/SM
// (independent barrier domains cover softmax/barrier stalls — R9 lever).
// ---------------------------------------------------------------------------
#define AROWB 144
#define ATILE (64 * AROWB)             // 9216 (64 keys x 64 dims f16)
#define ASTAGE (2 * ATILE)             // K|V = 18432
#define ASMEM (3 * ASTAGE)             // 55296  (2 CTAs = 110KB <= 228KB)

__global__ void __launch_bounds__(256, 2) attn_mma(
    const __half* __restrict__ QKV, __half* __restrict__ O)
{
    const int tid  = threadIdx.x;
    const int wid  = tid >> 5;
    const int lane = tid & 31;
    const int qtile = (gridDim.x - 1) - blockIdx.x;   // heavy tiles first
    const int bh = blockIdx.y;
    const int b  = bh >> 4;
    const int h  = bh & 15;
    const int bS = b * SS;
    const int qbase = qtile * 128 + wid * 16;

    const uint32_t sb = smem_u32(g_dsmem);

    // stage Q (128 rows x 64 dims f16)
#pragma unroll
    for (int i = 0; i < 4; i++) {
        const int idx = i * 256 + tid;
        const int r = idx >> 3, c = idx & 7;
        const size_t g = (size_t)(bS + qtile * 128 + r) * D3 + h * HD + c * 8;
        CP_ASYNC16(sb + r * AROWB + c * 16, QKV + g);
    }
    CP_COMMIT();
    CP_WAIT0();
    __syncthreads();

    // Q fragments, pre-scaled by 0.125*log2(e) -> base-2 logits
    uint32_t qf[4][4];
    const int a_row  = lane & 15;
    const int a_koff = (lane >> 4) * 16;
    {
        const uint32_t qr = sb + (wid * 16 + a_row) * AROWB + a_koff;
        const __half2 qs = __float2half2_rn(QSCALE);
#pragma unroll
        for (int ks = 0; ks < 4; ks++) {
            LDMATRIX_X4(qf[ks][0], qf[ks][1], qf[ks][2], qf[ks][3], qr + ks * 32);
#pragma unroll
            for (int j = 0; j < 4; j++) {
                __half2 v = *reinterpret_cast<__half2*>(&qf[ks][j]);
                v = __hmul2(v, qs);
                qf[ks][j] = *reinterpret_cast<uint32_t*>(&v);
            }
        }
    }
    __syncthreads();   // Q region reused for K/V ring

    auto load_kv = [&](int kt, int buf) {
        const int k0 = kt * 64;
        const uint32_t base = sb + buf * ASTAGE;
#pragma unroll
        for (int i = 0; i < 4; i++) {
            const int idx  = i * 256 + tid;     // 0..1023
            const int tile = idx >> 9;          // 0=K, 1=V
            const int r    = (idx >> 3) & 63;
            const int c    = idx & 7;
            const size_t g = (size_t)(bS + k0 + r) * D3 +
                             (tile ? 2 * DD : DD) + h * HD + c * 8;
            CP_ASYNC16(base + tile * ATILE + r * AROWB + c * 16, QKV + g);
        }
        CP_COMMIT();
    };

    float o[8][4];
#pragma unroll
    for (int n = 0; n < 8; n++)
#pragma unroll
        for (int j = 0; j < 4; j++) o[n][j] = 0.0f;
    float mrow[2] = {-1e30f, -1e30f};
    float lrow[2] = {0.0f, 0.0f};

    const int b_blk  = lane >> 3;
    const int b_row8 = lane & 7;
    const int b_noff = ((b_blk >> 1) << 3) + b_row8;
    const int b_koff = (b_blk & 1) * 16;
    const int v_row  = lane & 15;
    const int v_coff = ((lane >> 4) & 1) * 16;

    const int ntl = 2 * qtile + 2;
    load_kv(0, 0);
    if (ntl > 1) load_kv(1, 1);

    for (int kt = 0; kt < ntl; kt++) {
        if (kt < ntl - 1) CP_WAIT1();
        else              CP_WAIT0();
        __syncthreads();
        if (kt + 2 < ntl) load_kv(kt + 2, (kt + 2) % 3);

        const int k0 = kt * 64;
        if (k0 <= qbase + 15) {
            const uint32_t kbse = sb + (kt % 3) * ASTAGE;
            const uint32_t vbse = kbse + ATILE;

            // S = Q K^T (base-2 logits)
            float s[8][4];
#pragma unroll
            for (int n = 0; n < 8; n++)
#pragma unroll
                for (int j = 0; j < 4; j++) s[n][j] = 0.0f;

#pragma unroll
            for (int p = 0; p < 4; p++) {
#pragma unroll
                for (int ks = 0; ks < 4; ks++) {
                    uint32_t kf[4];
                    const uint32_t ar = kbse + (p * 16 + b_noff) * AROWB + ks * 32 + b_koff;
                    LDMATRIX_X4(kf[0], kf[1], kf[2], kf[3], ar);
                    uint32_t b0[2] = {kf[0], kf[1]}, b1[2] = {kf[2], kf[3]};
                    MMA_F16(s[2 * p],     qf[ks], b0);
                    MMA_F16(s[2 * p + 1], qf[ks], b1);
                }
            }

            // masking + online softmax (base 2)
            const bool need_mask = (k0 + 63 > qbase);
            const int row0 = qbase + (lane >> 2);
            const int colb = k0 + (lane & 3) * 2;
#pragma unroll
            for (int hf = 0; hf < 2; hf++) {
                const int row = row0 + 8 * hf;
                float mx = mrow[hf];
                if (need_mask) {
#pragma unroll
                    for (int n = 0; n < 8; n++) {
                        const int col = colb + 8 * n;
                        if (col > row)     s[n][2 * hf]     = -1e30f;
                        if (col + 1 > row) s[n][2 * hf + 1] = -1e30f;
                    }
                }
#pragma unroll
                for (int n = 0; n < 8; n++)
                    mx = fmaxf(mx, fmaxf(s[n][2 * hf], s[n][2 * hf + 1]));
                mx = fmaxf(mx, __shfl_xor_sync(0xffffffffu, mx, 1));
                mx = fmaxf(mx, __shfl_xor_sync(0xffffffffu, mx, 2));
                const float alpha = ex2(mrow[hf] - mx);
                lrow[hf] *= alpha;
#pragma unroll
                for (int n = 0; n < 8; n++) {
                    o[n][2 * hf]     *= alpha;
                    o[n][2 * hf + 1] *= alpha;
                }
                float ls = 0.0f;
#pragma unroll
                for (int n = 0; n < 8; n++) {
                    const float p0 = ex2(s[n][2 * hf]     - mx);
                    const float p1 = ex2(s[n][2 * hf + 1] - mx);
                    s[n][2 * hf] = p0; s[n][2 * hf + 1] = p1;
                    ls += p0 + p1;
                }
                lrow[hf] += ls;
                mrow[hf] = mx;
            }

            // O += P V
#pragma unroll
            for (int ks = 0; ks < 4; ks++) {
                uint32_t pf[4];
#pragma unroll
                for (int q2 = 0; q2 < 2; q2++) {
                    const float* pv = s[2 * ks + q2];
                    pf[q2 * 2]     = pack_f16(pv[0], pv[1]);
                    pf[q2 * 2 + 1] = pack_f16(pv[2], pv[3]);
                }
#pragma unroll
                for (int np = 0; np < 4; np++) {
                    uint32_t vf[4];
                    const uint32_t va = vbse + (ks * 16 + v_row) * AROWB + np * 32 + v_coff;
                    LDMATRIX_X4_T(vf[0], vf[1], vf[2], vf[3], va);
                    uint32_t v0[2] = {vf[0], vf[1]}, v1[2] = {vf[2], vf[3]};
                    MMA_F16(o[2 * np],     pf, v0);
                    MMA_F16(o[2 * np + 1], pf, v1);
                }
            }
        }
    }

    float inv[2];
#pragma unroll
    for (int hf = 0; hf < 2; hf++) {
        float l = lrow[hf];
        l += __shfl_xor_sync(0xffffffffu, l, 1);
        l += __shfl_xor_sync(0xffffffffu, l, 2);
        inv[hf] = 1.0f / l;
    }
    const int row0 = qbase + (lane >> 2);
    const int colb = h * HD + (lane & 3) * 2;
#pragma unroll
    for (int hf = 0; hf < 2; hf++) {
        const size_t rof = (size_t)(bS + row0 + 8 * hf) * DD;
#pragma unroll
        for (int n = 0; n < 8; n++)
            *(uint32_t*)(O + rof + colb + n * 8) =
                pack_f16(o[n][2 * hf] * inv[hf], o[n][2 * hf + 1] * inv[hf]);
    }
}

// ---------------------------------------------------------------------------
extern "C" void kernel_launch(void* const* d_in, const int* in_sizes, int n_in,
                              void* d_out, int out_size)
{
    const float* hidden   = (const float*)d_in[0];
    const float* c_attn_w = (const float*)d_in[1];
    const float* c_attn_b = (const float*)d_in[2];
    const float* c_proj_w = (const float*)d_in[3];
    const float* c_proj_b = (const float*)d_in[4];
    float* out = (float*)d_out;

    __half *qkv, *x, *a, *wq, *wp;
    cudaGetSymbolAddress((void**)&qkv, g_qkv);
    cudaGetSymbolAddress((void**)&x,   g_x);
    cudaGetSymbolAddress((void**)&a,   g_a);
    cudaGetSymbolAddress((void**)&wq,  g_wq);
    cudaGetSymbolAddress((void**)&wp,  g_wp);

    cudaFuncSetAttribute(gemm_mma, cudaFuncAttributeMaxDynamicSharedMemorySize, GSMEM);
    cudaFuncSetAttribute(attn_mma, cudaFuncAttributeMaxDynamicSharedMemorySize, ASMEM);

    wt_h<<<dim3(D3 / 32, DD / 32), dim3(32, 8)>>>(c_attn_w, wq, DD, D3);
    wt_h<<<dim3(DD / 32, DD / 32), dim3(32, 8)>>>(c_proj_w, wp, DD, DD);

    {
        const int n4 = NT * DD / 4;
        act_h<<<(n4 + 255) / 256, 256>>>((const float4*)hidden, (uint2*)x, n4);
    }

    // 1) QKV projection -> f16
    gemm_mma<<<dim3(D3 / 128, NT / 128), 128, GSMEM>>>(
        x, wq, c_attn_b, nullptr, qkv, NT, D3, DD);

    // 2) causal flash attention (64-key tiles, base-2 softmax, 2 CTAs/SM) -> f16
    attn_mma<<<dim3(SS / 128, BB * HH), 256, ASMEM>>>(qkv, a);

    // 3) output projection -> fp32
    gemm_mma<<<dim3(DD / 128, NT / 128), 128, GSMEM>>>(
        a, wp, c_proj_b, out, nullptr, NT, DD, DD);
}

// round 13
// speedup vs baseline: 1.2104x; 1.0026x over previous
#include <cuda_runtime.h>
#include <cuda_fp16.h>
#include <cstdint>

// Problem constants
#define BB 4
#define SS 2048
#define DD 1024
#define HH 16
#define HD 64
#define NT (BB * SS)        // 8192 tokens
#define D3 (3 * DD)         // 3072

#define WSC 64.0f           // weight scale 2^6
#define IWSC (1.0f / 64.0f)
#define QSCALE 0.1803368801f   // 0.125 * log2(e)

// ---------------------------------------------------------------------------
// Scratch (device globals — no runtime allocation)
// ---------------------------------------------------------------------------
static __device__ __half g_qkv[(size_t)NT * D3];
static __device__ __half g_x  [(size_t)NT * DD];
static __device__ __half g_a  [(size_t)NT * DD];
static __device__ __half g_wq [(size_t)D3 * DD];   // c_attn_w^T *64 [N][K]
static __device__ __half g_wp [(size_t)DD * DD];

// ---------------------------------------------------------------------------
__device__ __forceinline__ uint32_t smem_u32(const void* p) {
    uint32_t a;
    asm("{ .reg .u64 t; cvta.to.shared.u64 t, %1; cvt.u32.u64 %0, t; }" : "=r"(a) : "l"(p));
    return a;
}
__device__ __forceinline__ float ex2(float x) {
    float r;
    asm("ex2.approx.f32 %0, %1;" : "=f"(r) : "f"(x));
    return r;
}

#define CP_ASYNC16(saddr, gptr) \
    asm volatile("cp.async.cg.shared.global [%0], [%1], 16;" :: "r"(saddr), "l"(gptr) : "memory")
#define CP_COMMIT()  asm volatile("cp.async.commit_group;" ::: "memory")
#define CP_WAIT0()   asm volatile("cp.async.wait_group 0;" ::: "memory")
#define CP_WAIT1()   asm volatile("cp.async.wait_group 1;" ::: "memory")

#define LDMATRIX_X4(r0, r1, r2, r3, addr) \
    asm volatile("ldmatrix.sync.aligned.m8n8.x4.shared.b16 {%0,%1,%2,%3}, [%4];" \
        : "=r"(r0), "=r"(r1), "=r"(r2), "=r"(r3) : "r"(addr))

#define LDMATRIX_X4_T(r0, r1, r2, r3, addr) \
    asm volatile("ldmatrix.sync.aligned.m8n8.x4.trans.shared.b16 {%0,%1,%2,%3}, [%4];" \
        : "=r"(r0), "=r"(r1), "=r"(r2), "=r"(r3) : "r"(addr))

#define MMA_F16(c, a, b) \
    asm volatile("mma.sync.aligned.m16n8k16.row.col.f32.f16.f16.f32 " \
        "{%0,%1,%2,%3}, {%4,%5,%6,%7}, {%8,%9}, {%0,%1,%2,%3};" \
        : "+f"((c)[0]), "+f"((c)[1]), "+f"((c)[2]), "+f"((c)[3]) \
        : "r"((a)[0]), "r"((a)[1]), "r"((a)[2]), "r"((a)[3]), "r"((b)[0]), "r"((b)[1]))

__device__ __forceinline__ uint32_t pack_f16(float a, float b) {
    __half2 t = __floats2half2_rn(a, b);
    return *reinterpret_cast<uint32_t*>(&t);
}

// ---------------------------------------------------------------------------
// Conversion kernels
// ---------------------------------------------------------------------------
__global__ void act_h(const float4* __restrict__ x, uint2* __restrict__ o, int n4) {
    int i = blockIdx.x * blockDim.x + threadIdx.x;
    if (i >= n4) return;
    float4 v = x[i];
    uint2 r;
    r.x = pack_f16(v.x, v.y);
    r.y = pack_f16(v.z, v.w);
    o[i] = r;
}

// Both weight transposes in one launch: bx<96 -> c_attn_w (N=3072),
// bx>=96 -> c_proj_w (N=1024). K=1024 for both.
__global__ void wt_both(const float* __restrict__ Wq, __half* __restrict__ oq,
                        const float* __restrict__ Wp, __half* __restrict__ op_) {
    __shared__ float t[32][33];
    const int K = DD;
    const float* W;
    __half* o;
    int N, bx = blockIdx.x;
    if (bx < 96) { W = Wq; o = oq; N = D3; }
    else         { W = Wp; o = op_; N = DD; bx -= 96; }
    const int kb = blockIdx.y * 32, nb = bx * 32;
    const int tx = threadIdx.x, ty = threadIdx.y;
#pragma unroll
    for (int i = 0; i < 32; i += 8)
        t[ty + i][tx] = W[(size_t)(kb + ty + i) * N + nb + tx];
    __syncthreads();
#pragma unroll
    for (int i = 0; i < 32; i += 8)
        o[(size_t)(nb + ty + i) * K + kb + tx] = __float2half_rn(t[tx][ty + i] * WSC);
}

// ---------------------------------------------------------------------------
// f16 HMMA GEMM v5 (QKV): CTA tile 128x64, 4 warps (2x2), warp tile 64x32.
// BK=64, 2-stage ring, one barrier/stage, 3 CTAs/SM (fine wave quantization:
// 3072 CTAs / 444 slots = 6.92 -> ~1% tail vs 15.6% at 128x128).
// ---------------------------------------------------------------------------
#define GROWB 144
#define G6ATILE (128 * GROWB)          // 18432
#define G6BTILE (64 * GROWB)           // 9216
#define G6STAGE (G6ATILE + G6BTILE)    // 27648
#define G6SMEM  (2 * G6STAGE)          // 55296

extern __shared__ char g_dsmem[];

__global__ void __launch_bounds__(128, 3) gemm_mma64(
    const __half* __restrict__ A, const __half* __restrict__ B,
    const float* __restrict__ bias, __half* __restrict__ Ch,
    int M, int N, int K)
{
    const int tid  = threadIdx.x;
    const int wid  = tid >> 5;
    const int lane = tid & 31;
    const int wm   = wid >> 1;        // 0..1 (64 M-rows)
    const int wn   = wid & 1;         // 0..1 (32 N-cols)
    const int bm = blockIdx.y, bn = blockIdx.x;

    const __half* Ab = A + (size_t)(bm * 128) * K;
    const __half* Bb = B + (size_t)(bn * 64) * K;

    const uint32_t sb = smem_u32(g_dsmem);

    float acc[4][4][4];
#pragma unroll
    for (int i = 0; i < 4; i++)
#pragma unroll
        for (int j = 0; j < 4; j++)
#pragma unroll
            for (int v = 0; v < 4; v++) acc[i][j][v] = 0.0f;

    const int NS = K >> 6;            // 16 stages of K=64

    // stage = A 128x8 + B 64x8 = 1536 chunks; 12 per thread
    auto load_stage = [&](int s, int buf) {
        const int k0 = s << 6;
        const uint32_t base = sb + buf * G6STAGE;
#pragma unroll
        for (int i = 0; i < 8; i++) {
            const int idx = i * 128 + tid;
            const int r = idx >> 3, c = idx & 7;
            CP_ASYNC16(base + r * GROWB + c * 16, Ab + (size_t)r * K + k0 + c * 8);
        }
#pragma unroll
        for (int i = 0; i < 4; i++) {
            const int idx = i * 128 + tid;
            const int r = idx >> 3, c = idx & 7;
            CP_ASYNC16(base + G6ATILE + r * GROWB + c * 16, Bb + (size_t)r * K + k0 + c * 8);
        }
        CP_COMMIT();
    };

    load_stage(0, 0);

    const int a_row  = (lane & 15);
    const int a_koff = (lane >> 4) * 16;
    const int b_blk  = lane >> 3;
    const int b_row8 = lane & 7;
    const int b_noff = ((b_blk >> 1) << 3) + b_row8;
    const int b_koff = (b_blk & 1) * 16;

    for (int s = 0; s < NS; s++) {
        CP_WAIT0();
        __syncthreads();
        // buffer (s+1)&1: its compute (stage s-1) finished before the barrier
        if (s + 1 < NS) load_stage(s + 1, (s + 1) & 1);

        const uint32_t st = sb + (s & 1) * G6STAGE;
#pragma unroll
        for (int ks = 0; ks < 4; ks++) {
            const int kb = ks * 32;

            uint32_t af[4][4], bf[4][2];
#pragma unroll
            for (int mt = 0; mt < 4; mt++) {
                const uint32_t ar = st + (wm * 64 + mt * 16 + a_row) * GROWB + kb + a_koff;
                LDMATRIX_X4(af[mt][0], af[mt][1], af[mt][2], af[mt][3], ar);
            }
#pragma unroll
            for (int p = 0; p < 2; p++) {
                const uint32_t br = st + G6ATILE +
                    (wn * 32 + p * 16 + b_noff) * GROWB + kb + b_koff;
                LDMATRIX_X4(bf[2 * p][0], bf[2 * p][1], bf[2 * p + 1][0], bf[2 * p + 1][1], br);
            }
#pragma unroll
            for (int mt = 0; mt < 4; mt++)
#pragma unroll
                for (int nt = 0; nt < 4; nt++)
                    MMA_F16(acc[mt][nt], af[mt], bf[nt]);
        }
    }

    const int r0 = bm * 128 + wm * 64 + (lane >> 2);
    const int c0 = bn * 64 + wn * 32 + (lane & 3) * 2;
#pragma unroll
    for (int mt = 0; mt < 4; mt++)
#pragma unroll
        for (int nt = 0; nt < 4; nt++) {
            const int row = r0 + mt * 16;
            const int col = c0 + nt * 8;
            const float b0 = bias[col], b1 = bias[col + 1];
            *(uint32_t*)(Ch + (size_t)row * N + col) =
                pack_f16(acc[mt][nt][0] * IWSC + b0, acc[mt][nt][1] * IWSC + b1);
            *(uint32_t*)(Ch + (size_t)(row + 8) * N + col) =
                pack_f16(acc[mt][nt][2] * IWSC + b0, acc[mt][nt][3] * IWSC + b1);
        }
}

// ---------------------------------------------------------------------------
// f16 HMMA GEMM v4 (proj, frozen since R9): 128x128 CTA, 4 warps, 64x64/warp,
// BK=64, 3-stage ring, one barrier/stage, 2 CTAs/SM. fp32 output.
// ---------------------------------------------------------------------------
#define GATILE (128 * GROWB)           // 18432
#define GSTAGE (2 * GATILE)            // 36864
#define GSMEM  (3 * GSTAGE)            // 110592

__global__ void __launch_bounds__(128, 2) gemm_mma(
    const __half* __restrict__ A, const __half* __restrict__ B,
    const float* __restrict__ bias, float* __restrict__ Cf,
    int M, int N, int K)
{
    const int tid  = threadIdx.x;
    const int wid  = tid >> 5;
    const int lane = tid & 31;
    const int wm   = wid >> 1;
    const int wn   = wid & 1;
    const int bm = blockIdx.y, bn = blockIdx.x;

    const __half* Ab = A + (size_t)(bm * 128) * K;
    const __half* Bb = B + (size_t)(bn * 128) * K;

    const uint32_t sb = smem_u32(g_dsmem);

    float acc[4][8][4];
#pragma unroll
    for (int i = 0; i < 4; i++)
#pragma unroll
        for (int j = 0; j < 8; j++)
#pragma unroll
            for (int v = 0; v < 4; v++) acc[i][j][v] = 0.0f;

    const int NS = K >> 6;

    auto load_stage = [&](int s, int buf) {
        const int k0 = s << 6;
        const uint32_t base = sb + buf * GSTAGE;
#pragma unroll
        for (int i = 0; i < 8; i++) {
            const int idx = i * 128 + tid;
            const int r = idx >> 3, c = idx & 7;
            CP_ASYNC16(base + r * GROWB + c * 16, Ab + (size_t)r * K + k0 + c * 8);
        }
#pragma unroll
        for (int i = 0; i < 8; i++) {
            const int idx = i * 128 + tid;
            const int r = idx >> 3, c = idx & 7;
            CP_ASYNC16(base + GATILE + r * GROWB + c * 16, Bb + (size_t)r * K + k0 + c * 8);
        }
        CP_COMMIT();
    };

    load_stage(0, 0);
    load_stage(1, 1);

    const int a_row  = (lane & 15);
    const int a_koff = (lane >> 4) * 16;
    const int b_blk  = lane >> 3;
    const int b_row8 = lane & 7;
    const int b_noff = ((b_blk >> 1) << 3) + b_row8;
    const int b_koff = (b_blk & 1) * 16;

    for (int s = 0; s < NS; s++) {
        if (s < NS - 1) CP_WAIT1();
        else            CP_WAIT0();
        __syncthreads();
        if (s + 2 < NS) load_stage(s + 2, (s + 2) % 3);

        const uint32_t st = sb + (s % 3) * GSTAGE;
#pragma unroll
        for (int ks = 0; ks < 4; ks++) {
            const int kb = ks * 32;

            uint32_t af[4][4], bf[8][2];
#pragma unroll
            for (int mt = 0; mt < 4; mt++) {
                const uint32_t ar = st + (wm * 64 + mt * 16 + a_row) * GROWB + kb + a_koff;
                LDMATRIX_X4(af[mt][0], af[mt][1], af[mt][2], af[mt][3], ar);
            }
#pragma unroll
            for (int p = 0; p < 4; p++) {
                const uint32_t br = st + GATILE +
                    (wn * 64 + p * 16 + b_noff) * GROWB + kb + b_koff;
                LDMATRIX_X4(bf[2 * p][0], bf[2 * p][1], bf[2 * p + 1][0], bf[2 * p + 1][1], br);
            }
#pragma unroll
            for (int mt = 0; mt < 4; mt++)
#pragma unroll
                for (int nt = 0; nt < 8; nt++)
                    MMA_F16(acc[mt][nt], af[mt], bf[nt]);
        }
    }

    const int r0 = bm * 128 + wm * 64 + (lane >> 2);
    const int c0 = bn * 128 + wn * 64 + (lane & 3) * 2;
#pragma unroll
    for (int mt = 0; mt < 4; mt++)
#pragma unroll
        for (int nt = 0; nt < 8; nt++) {
            const int row = r0 + mt * 16;
            const int col = c0 + nt * 8;
            float2 o0, o1;
            o0.x = acc[mt][nt][0] * IWSC + bias[col];
            o0.y = acc[mt][nt][1] * IWSC + bias[col + 1];
            o1.x = acc[mt][nt][2] * IWSC + bias[col];
            o1.y = acc[mt][nt][3] * IWSC + bias[col + 1];
            *(float2*)(Cf + (size_t)row * N + col) = o0;
            *(float2*)(Cf + (size_t)(row + 8) * N + col) = o1;
        }
}

// ---------------------------------------------------------------------------
// Tensor-core causal flash attention v5: R12 structure + alpha-skip
// (skip o/l rescale when running max unchanged — warp-uniform branch).
// ---------------------------------------------------------------------------
#define AROWB 144
#define ATILE (64 * AROWB)             // 9216
#define ASTAGE (2 * ATILE)             // 18432
#define ASMEM (3 * ASTAGE)             // 55296

__global__ void __launch_bounds__(256, 2) attn_mma(
    const __half* __restrict__ QKV, __half* __restrict__ O)
{
    const int tid  = threadIdx.x;
    const int wid  = tid >> 5;
    const int lane = tid & 31;
    const int qtile = (gridDim.x - 1) - blockIdx.x;   // heavy tiles first
    const int bh = blockIdx.y;
    const int b  = bh >> 4;
    const int h  = bh & 15;
    const int bS = b * SS;
    const int qbase = qtile * 128 + wid * 16;

    const uint32_t sb = smem_u32(g_dsmem);

    // stage Q (128 rows x 64 dims f16)
#pragma unroll
    for (int i = 0; i < 4; i++) {
        const int idx = i * 256 + tid;
        const int r = idx >> 3, c = idx & 7;
        const size_t g = (size_t)(bS + qtile * 128 + r) * D3 + h * HD + c * 8;
        CP_ASYNC16(sb + r * AROWB + c * 16, QKV + g);
    }
    CP_COMMIT();
    CP_WAIT0();
    __syncthreads();

    // Q fragments, pre-scaled by 0.125*log2(e)
    uint32_t qf[4][4];
    const int a_row  = lane & 15;
    const int a_koff = (lane >> 4) * 16;
    {
        const uint32_t qr = sb + (wid * 16 + a_row) * AROWB + a_koff;
        const __half2 qs = __float2half2_rn(QSCALE);
#pragma unroll
        for (int ks = 0; ks < 4; ks++) {
            LDMATRIX_X4(qf[ks][0], qf[ks][1], qf[ks][2], qf[ks][3], qr + ks * 32);
#pragma unroll
            for (int j = 0; j < 4; j++) {
                __half2 v = *reinterpret_cast<__half2*>(&qf[ks][j]);
                v = __hmul2(v, qs);
                qf[ks][j] = *reinterpret_cast<uint32_t*>(&v);
            }
        }
    }
    __syncthreads();   // Q region reused for K/V ring

    auto load_kv = [&](int kt, int buf) {
        const int k0 = kt * 64;
        const uint32_t base = sb + buf * ASTAGE;
#pragma unroll
        for (int i = 0; i < 4; i++) {
            const int idx  = i * 256 + tid;
            const int tile = idx >> 9;
            const int r    = (idx >> 3) & 63;
            const int c    = idx & 7;
            const size_t g = (size_t)(bS + k0 + r) * D3 +
                             (tile ? 2 * DD : DD) + h * HD + c * 8;
            CP_ASYNC16(base + tile * ATILE + r * AROWB + c * 16, QKV + g);
        }
        CP_COMMIT();
    };

    float o[8][4];
#pragma unroll
    for (int n = 0; n < 8; n++)
#pragma unroll
        for (int j = 0; j < 4; j++) o[n][j] = 0.0f;
    float mrow[2] = {-1e30f, -1e30f};
    float lrow[2] = {0.0f, 0.0f};

    const int b_blk  = lane >> 3;
    const int b_row8 = lane & 7;
    const int b_noff = ((b_blk >> 1) << 3) + b_row8;
    const int b_koff = (b_blk & 1) * 16;
    const int v_row  = lane & 15;
    const int v_coff = ((lane >> 4) & 1) * 16;

    const int ntl = 2 * qtile + 2;
    load_kv(0, 0);
    if (ntl > 1) load_kv(1, 1);

    for (int kt = 0; kt < ntl; kt++) {
        if (kt < ntl - 1) CP_WAIT1();
        else              CP_WAIT0();
        __syncthreads();
        if (kt + 2 < ntl) load_kv(kt + 2, (kt + 2) % 3);

        const int k0 = kt * 64;
        if (k0 <= qbase + 15) {
            const uint32_t kbse = sb + (kt % 3) * ASTAGE;
            const uint32_t vbse = kbse + ATILE;

            // S = Q K^T (base-2 logits)
            float s[8][4];
#pragma unroll
            for (int n = 0; n < 8; n++)
#pragma unroll
                for (int j = 0; j < 4; j++) s[n][j] = 0.0f;

#pragma unroll
            for (int p = 0; p < 4; p++) {
#pragma unroll
                for (int ks = 0; ks < 4; ks++) {
                    uint32_t kf[4];
                    const uint32_t ar = kbse + (p * 16 + b_noff) * AROWB + ks * 32 + b_koff;
                    LDMATRIX_X4(kf[0], kf[1], kf[2], kf[3], ar);
                    uint32_t b0[2] = {kf[0], kf[1]}, b1[2] = {kf[2], kf[3]};
                    MMA_F16(s[2 * p],     qf[ks], b0);
                    MMA_F16(s[2 * p + 1], qf[ks], b1);
                }
            }

            // masking + online softmax (base 2, alpha-skip)
            const bool need_mask = (k0 + 63 > qbase);
            const int row0 = qbase + (lane >> 2);
            const int colb = k0 + (lane & 3) * 2;
#pragma unroll
            for (int hf = 0; hf < 2; hf++) {
                const int row = row0 + 8 * hf;
                float mx = mrow[hf];
                if (need_mask) {
#pragma unroll
                    for (int n = 0; n < 8; n++) {
                        const int col = colb + 8 * n;
                        if (col > row)     s[n][2 * hf]     = -1e30f;
                        if (col + 1 > row) s[n][2 * hf + 1] = -1e30f;
                    }
                }
#pragma unroll
                for (int n = 0; n < 8; n++)
                    mx = fmaxf(mx, fmaxf(s[n][2 * hf], s[n][2 * hf + 1]));
                mx = fmaxf(mx, __shfl_xor_sync(0xffffffffu, mx, 1));
                mx = fmaxf(mx, __shfl_xor_sync(0xffffffffu, mx, 2));
                if (mx > mrow[hf]) {       // warp-uniform: rescale only if max moved
                    const float alpha = ex2(mrow[hf] - mx);
                    lrow[hf] *= alpha;
#pragma unroll
                    for (int n = 0; n < 8; n++) {
                        o[n][2 * hf]     *= alpha;
                        o[n][2 * hf + 1] *= alpha;
                    }
                    mrow[hf] = mx;
                }
                float ls = 0.0f;
#pragma unroll
                for (int n = 0; n < 8; n++) {
                    const float p0 = ex2(s[n][2 * hf]     - mx);
                    const float p1 = ex2(s[n][2 * hf + 1] - mx);
                    s[n][2 * hf] = p0; s[n][2 * hf + 1] = p1;
                    ls += p0 + p1;
                }
                lrow[hf] += ls;
            }

            // O += P V
#pragma unroll
            for (int ks = 0; ks < 4; ks++) {
                uint32_t pf[4];
#pragma unroll
                for (int q2 = 0; q2 < 2; q2++) {
                    const float* pv = s[2 * ks + q2];
                    pf[q2 * 2]     = pack_f16(pv[0], pv[1]);
                    pf[q2 * 2 + 1] = pack_f16(pv[2], pv[3]);
                }
#pragma unroll
                for (int np = 0; np < 4; np++) {
                    uint32_t vf[4];
                    const uint32_t va = vbse + (ks * 16 + v_row) * AROWB + np * 32 + v_coff;
                    LDMATRIX_X4_T(vf[0], vf[1], vf[2], vf[3], va);
                    uint32_t v0[2] = {vf[0], vf[1]}, v1[2] = {vf[2], vf[3]};
                    MMA_F16(o[2 * np],     pf, v0);
                    MMA_F16(o[2 * np + 1], pf, v1);
                }
            }
        }
    }

    float inv[2];
#pragma unroll
    for (int hf = 0; hf < 2; hf++) {
        float l = lrow[hf];
        l += __shfl_xor_sync(0xffffffffu, l, 1);
        l += __shfl_xor_sync(0xffffffffu, l, 2);
        inv[hf] = 1.0f / l;
    }
    const int row0 = qbase + (lane >> 2);
    const int colb = h * HD + (lane & 3) * 2;
#pragma unroll
    for (int hf = 0; hf < 2; hf++) {
        const size_t rof = (size_t)(bS + row0 + 8 * hf) * DD;
#pragma unroll
        for (int n = 0; n < 8; n++)
            *(uint32_t*)(O + rof + colb + n * 8) =
                pack_f16(o[n][2 * hf] * inv[hf], o[n][2 * hf + 1] * inv[hf]);
    }
}

// ---------------------------------------------------------------------------
extern "C" void kernel_launch(void* const* d_in, const int* in_sizes, int n_in,
                              void* d_out, int out_size)
{
    const float* hidden   = (const float*)d_in[0];
    const float* c_attn_w = (const float*)d_in[1];
    const float* c_attn_b = (const float*)d_in[2];
    const float* c_proj_w = (const float*)d_in[3];
    const float* c_proj_b = (const float*)d_in[4];
    float* out = (float*)d_out;

    __half *qkv, *x, *a, *wq, *wp;
    cudaGetSymbolAddress((void**)&qkv, g_qkv);
    cudaGetSymbolAddress((void**)&x,   g_x);
    cudaGetSymbolAddress((void**)&a,   g_a);
    cudaGetSymbolAddress((void**)&wq,  g_wq);
    cudaGetSymbolAddress((void**)&wp,  g_wp);

    cudaFuncSetAttribute(gemm_mma64, cudaFuncAttributeMaxDynamicSharedMemorySize, G6SMEM);
    cudaFuncSetAttribute(gemm_mma,   cudaFuncAttributeMaxDynamicSharedMemorySize, GSMEM);
    cudaFuncSetAttribute(attn_mma,   cudaFuncAttributeMaxDynamicSharedMemorySize, ASMEM);

    // prep: activations + both weight transposes (2 launches)
    {
        const int n4 = NT * DD / 4;
        act_h<<<(n4 + 255) / 256, 256>>>((const float4*)hidden, (uint2*)x, n4);
    }
    wt_both<<<dim3(128, DD / 32), dim3(32, 8)>>>(c_attn_w, wq, c_proj_w, wp);

    // 1) QKV projection -> f16 (128x64 tiles, 3 CTAs/SM, ~1% wave tail)
    gemm_mma64<<<dim3(D3 / 64, NT / 128), 128, G6SMEM>>>(
        x, wq, c_attn_b, qkv, NT, D3, DD);

    // 2) causal flash attention -> f16
    attn_mma<<<dim3(SS / 128, BB * HH), 256, ASMEM>>>(qkv, a);

    // 3) output projection -> fp32
    gemm_mma<<<dim3(DD / 128, NT / 128), 128, GSMEM>>>(
        a, wp, c_proj_b, out, NT, DD, DD);
}